// round 10
// baseline (speedup 1.0000x reference)
#include <cuda_runtime.h>
#include <cuda_bf16.h>
#include <cstdint>
#include <math.h>

#define SEQ   128
#define BAT   32
#define EH    512
#define EO    256
#define HID   512
#define G3    1536
#define OUTD  256
#define MROWS (SEQ*BAT)
#define THRESH 1e-6f

typedef unsigned long long ull;
typedef unsigned int u32;

// ---------------- scratch (device globals; no allocation allowed) ----------
__device__ float g_emb[MROWS * EO];          // 4 MB
__device__ float g_xproj[MROWS * G3];        // 25 MB
__device__ float g_h[2][BAT * HID];          // ping-pong hidden state
// flags: 8 domains (bgp 0..3 x grp 0..1) x 32 CTAs, 128B apart. Reset at end.
__device__ __align__(128) unsigned g_bflags[8 * 32 * 32];

// ---------------- f32x2 helpers -------------------------------------------
__device__ __forceinline__ ull pack2(float lo, float hi) {
    ull r; asm("mov.b64 %0, {%1, %2};" : "=l"(r) : "f"(lo), "f"(hi)); return r;
}
__device__ __forceinline__ float2 unpack2(ull v) {
    float2 r; asm("mov.b64 {%0, %1}, %2;" : "=f"(r.x), "=f"(r.y) : "l"(v)); return r;
}
__device__ __forceinline__ void fma2(ull& d, ull a, ull b) {
    asm("fma.rn.f32x2 %0, %1, %2, %3;" : "=l"(d) : "l"(a), "l"(b), "l"(d));
}
__device__ __forceinline__ float thr(float v) { return v > THRESH ? v : 0.0f; }

// ---------------- acquire/release helpers ----------------------------------
__device__ __forceinline__ unsigned ld_acq(const unsigned* p) {
    unsigned v; asm volatile("ld.acquire.gpu.u32 %0, [%1];" : "=r"(v) : "l"(p)); return v;
}
__device__ __forceinline__ void st_rel(unsigned* p, unsigned v) {
    asm volatile("st.release.gpu.u32 [%0], %1;" :: "l"(p), "r"(v));
}

// ===========================================================================
// GEMM 1 (fused embedding): emb = thr( thr(W1[tok]+b1) @ W2 + b2 )
//   M=4096 K=512 N=256. Tile 128x64x16, 256 threads, 8x4 micro-tile (f32x2).
// ===========================================================================
__global__ __launch_bounds__(256) void gemm_embed_kernel(
    const int* __restrict__ tok, const float* __restrict__ W1,
    const float* __restrict__ b1, const float* __restrict__ W2,
    const float* __restrict__ b2)
{
    __shared__ __align__(16) float As[16][132];
    __shared__ __align__(16) float Bs[16][68];

    const int bm = blockIdx.x, bn = blockIdx.y;
    const int t  = threadIdx.x;
    const int tx = t & 15, ty = t >> 4;

    const int arow = t >> 2, aseg = t & 3;
    const int tk0 = tok[bm * 128 + arow];
    const int tk1 = tok[bm * 128 + arow + 64];
    const float* w1r0 = W1 + (size_t)tk0 * EH;
    const float* w1r1 = W1 + (size_t)tk1 * EH;
    const int bk = t >> 4, bseg = t & 15;

    ull acc[8][2] = {};

    for (int kt = 0; kt < EH; kt += 16) {
        float4 bb = *(const float4*)(b1 + kt + aseg * 4);
        float4 a0 = *(const float4*)(w1r0 + kt + aseg * 4);
        float4 a1 = *(const float4*)(w1r1 + kt + aseg * 4);
        a0.x = thr(a0.x + bb.x); a0.y = thr(a0.y + bb.y);
        a0.z = thr(a0.z + bb.z); a0.w = thr(a0.w + bb.w);
        a1.x = thr(a1.x + bb.x); a1.y = thr(a1.y + bb.y);
        a1.z = thr(a1.z + bb.z); a1.w = thr(a1.w + bb.w);
        As[aseg * 4 + 0][arow] = a0.x;  As[aseg * 4 + 0][arow + 64] = a1.x;
        As[aseg * 4 + 1][arow] = a0.y;  As[aseg * 4 + 1][arow + 64] = a1.y;
        As[aseg * 4 + 2][arow] = a0.z;  As[aseg * 4 + 2][arow + 64] = a1.z;
        As[aseg * 4 + 3][arow] = a0.w;  As[aseg * 4 + 3][arow + 64] = a1.w;
        *(float4*)&Bs[bk][bseg * 4] =
            *(const float4*)(W2 + (size_t)(kt + bk) * EO + bn * 64 + bseg * 4);
        __syncthreads();
        #pragma unroll
        for (int kk = 0; kk < 16; kk++) {
            float4 av0 = *(const float4*)&As[kk][ty * 8];
            float4 av1 = *(const float4*)&As[kk][ty * 8 + 4];
            ulonglong2 bv = *(const ulonglong2*)&Bs[kk][tx * 4];
            ull a;
            a = pack2(av0.x, av0.x); fma2(acc[0][0], a, bv.x); fma2(acc[0][1], a, bv.y);
            a = pack2(av0.y, av0.y); fma2(acc[1][0], a, bv.x); fma2(acc[1][1], a, bv.y);
            a = pack2(av0.z, av0.z); fma2(acc[2][0], a, bv.x); fma2(acc[2][1], a, bv.y);
            a = pack2(av0.w, av0.w); fma2(acc[3][0], a, bv.x); fma2(acc[3][1], a, bv.y);
            a = pack2(av1.x, av1.x); fma2(acc[4][0], a, bv.x); fma2(acc[4][1], a, bv.y);
            a = pack2(av1.y, av1.y); fma2(acc[5][0], a, bv.x); fma2(acc[5][1], a, bv.y);
            a = pack2(av1.z, av1.z); fma2(acc[6][0], a, bv.x); fma2(acc[6][1], a, bv.y);
            a = pack2(av1.w, av1.w); fma2(acc[7][0], a, bv.x); fma2(acc[7][1], a, bv.y);
        }
        __syncthreads();
    }
    const int m0 = bm * 128 + ty * 8, n0 = bn * 64 + tx * 4;
    #pragma unroll
    for (int i = 0; i < 8; i++) {
        #pragma unroll
        for (int p = 0; p < 2; p++) {
            float2 v = unpack2(acc[i][p]);
            int n = n0 + p * 2;
            v.x = thr(v.x + b2[n]);
            v.y = thr(v.y + b2[n + 1]);
            *(float2*)&g_emb[(size_t)(m0 + i) * EO + n] = v;
        }
    }
}

// ===========================================================================
// GEMM 2 (NT): xproj = emb @ W_ih^T + b_ih   M=4096 K=256 N=1536
//   Tile 128x128x16, 256 threads, 8x8 micro-tile (f32x2).
// ===========================================================================
__global__ __launch_bounds__(256) void gemm_xproj_kernel(
    const float* __restrict__ W_ih, const float* __restrict__ b_ih)
{
    __shared__ __align__(16) float As[16][132];
    __shared__ __align__(16) float Bs[16][132];

    const int bm = blockIdx.x, bn = blockIdx.y;
    const int t  = threadIdx.x;
    const int tx = t & 15, ty = t >> 4;
    const int row = t >> 2, seg = t & 3;

    ull acc[8][4] = {};

    for (int kt = 0; kt < EO; kt += 16) {
        #pragma unroll
        for (int i = 0; i < 2; i++) {
            int r = row + i * 64;
            float4 a4 = *(const float4*)(g_emb + (size_t)(bm * 128 + r) * EO + kt + seg * 4);
            As[seg * 4 + 0][r] = a4.x;
            As[seg * 4 + 1][r] = a4.y;
            As[seg * 4 + 2][r] = a4.z;
            As[seg * 4 + 3][r] = a4.w;
            float4 b4 = *(const float4*)(W_ih + (size_t)(bn * 128 + r) * EO + kt + seg * 4);
            Bs[seg * 4 + 0][r] = b4.x;
            Bs[seg * 4 + 1][r] = b4.y;
            Bs[seg * 4 + 2][r] = b4.z;
            Bs[seg * 4 + 3][r] = b4.w;
        }
        __syncthreads();
        #pragma unroll
        for (int kk = 0; kk < 16; kk++) {
            float4 av0 = *(const float4*)&As[kk][ty * 8];
            float4 av1 = *(const float4*)&As[kk][ty * 8 + 4];
            ulonglong2 b01 = *(const ulonglong2*)&Bs[kk][tx * 8];
            ulonglong2 b23 = *(const ulonglong2*)&Bs[kk][tx * 8 + 4];
            ull a;
            a = pack2(av0.x, av0.x); fma2(acc[0][0], a, b01.x); fma2(acc[0][1], a, b01.y); fma2(acc[0][2], a, b23.x); fma2(acc[0][3], a, b23.y);
            a = pack2(av0.y, av0.y); fma2(acc[1][0], a, b01.x); fma2(acc[1][1], a, b01.y); fma2(acc[1][2], a, b23.x); fma2(acc[1][3], a, b23.y);
            a = pack2(av0.z, av0.z); fma2(acc[2][0], a, b01.x); fma2(acc[2][1], a, b01.y); fma2(acc[2][2], a, b23.x); fma2(acc[2][3], a, b23.y);
            a = pack2(av0.w, av0.w); fma2(acc[3][0], a, b01.x); fma2(acc[3][1], a, b01.y); fma2(acc[3][2], a, b23.x); fma2(acc[3][3], a, b23.y);
            a = pack2(av1.x, av1.x); fma2(acc[4][0], a, b01.x); fma2(acc[4][1], a, b01.y); fma2(acc[4][2], a, b23.x); fma2(acc[4][3], a, b23.y);
            a = pack2(av1.y, av1.y); fma2(acc[5][0], a, b01.x); fma2(acc[5][1], a, b01.y); fma2(acc[5][2], a, b23.x); fma2(acc[5][3], a, b23.y);
            a = pack2(av1.z, av1.z); fma2(acc[6][0], a, b01.x); fma2(acc[6][1], a, b01.y); fma2(acc[6][2], a, b23.x); fma2(acc[6][3], a, b23.y);
            a = pack2(av1.w, av1.w); fma2(acc[7][0], a, b01.x); fma2(acc[7][1], a, b01.y); fma2(acc[7][2], a, b23.x); fma2(acc[7][3], a, b23.y);
        }
        __syncthreads();
    }
    const int m0 = bm * 128 + ty * 8, n0 = bn * 128 + tx * 8;
    #pragma unroll
    for (int i = 0; i < 8; i++) {
        #pragma unroll
        for (int p = 0; p < 4; p++) {
            float2 v = unpack2(acc[i][p]);
            int n = n0 + p * 2;
            v.x += b_ih[n];
            v.y += b_ih[n + 1];
            *(float2*)&g_xproj[(size_t)(m0 + i) * G3 + n] = v;
        }
    }
}

// ===========================================================================
// GRU: persistent, 128 CTAs x 128 threads. CTA = (bgp 0..3, jg 0..31).
// Two independent 4-row groups per CTA (A = rows bgp*8..+4, B = +4..+8),
// software-pipelined so each group's barrier RTT hides behind the other
// group's compute. Leaderless all-to-all flag barriers (one domain per
// (bgp,grp); warp-1/2 lanes poll the 32 peer flags directly).
// Thread = (jw 0..15, bh 0..1, ks 0..3); q = bh*4+ks = k-phase (k-split 8);
// W cols swizzled by (kq&7): quarter-warp bank-exact (W 4wf, h 1wf).
// ===========================================================================
#define GRU_NCTA   128
#define GRU_WS     (3 * 128 * 16 * 4)      // floats (96 KB)
#define GRU_HSTR   516
#define GRU_SMEMB  ((GRU_WS + 8 * GRU_HSTR) * 4)
#define FINALV     ((unsigned)(SEQ + 1))

__global__ __launch_bounds__(128, 1) void gru_kernel(
    const float* __restrict__ W_hh, const float* __restrict__ b_hh,
    const float* __restrict__ W3,   const float* __restrict__ b3,
    float* __restrict__ out)
{
    extern __shared__ __align__(16) float smem[];
    float* w_s = smem;                 // [gate][kq][col16][4], col swizzled
    float* h_s = smem + GRU_WS;        // [8][516]: rows 0-3 grp A, 4-7 grp B

    const int t   = threadIdx.x;
    const int bid = blockIdx.x;
    const int jg  = bid & 31;
    const int bgp = bid >> 5;
    const int domA = bgp * 2, domB = bgp * 2 + 1;

    // stage W_hh slice, columns swizzled by (kq & 7)
    for (int idx = t; idx < 3 * 16 * 128; idx += 128) {
        int kq = idx & 127;
        int jj = (idx >> 7) & 15;
        int g  = idx >> 11;
        float4 v = *(const float4*)(W_hh + ((size_t)(g * HID + jg * 16 + jj)) * HID + kq * 4);
        int c = (jj + (kq & 7)) & 15;
        *(float4*)(w_s + ((g * 128 + kq) * 16 + c) * 4) = v;
    }
    // zero h_s (h(-1) = 0); g_h needs no init (buffer 0 never read)
    for (int idx = t; idx < 8 * GRU_HSTR; idx += 128) h_s[idx] = 0.0f;
    __syncthreads();

    const int ks = t & 3;
    const int bh = (t >> 2) & 1;
    const int jw = t >> 3;                // 0..15
    const int q  = bh * 4 + ks;           // 0..7 k-phase
    const int jglob = jg * 16 + jw;
    const bool fin  = (q < 4);
    const int mfin  = q & 3;              // row-in-group finalized by fin lanes

    const float bhr = b_hh[jglob];
    const float bhz = b_hh[HID + jglob];
    const float bhn = b_hh[2 * HID + jglob];

    const float* wcol = w_s + ((jw + q) & 15) * 4;

    #define COMPUTE_GROUP(GRP, NXT, STEP) do {                                 \
        const float* hbase = h_s + (GRP) * 4 * GRU_HSTR;                       \
        const int brow = bgp * 8 + (GRP) * 4 + mfin;                           \
        float xr = 0.f, xz = 0.f, xn = 0.f;                                    \
        if (fin) {                                                             \
            size_t xb = ((size_t)((STEP) * BAT + brow)) * G3 + jglob;          \
            xr = __ldcg(g_xproj + xb);                                         \
            xz = __ldcg(g_xproj + xb + HID);                                   \
            xn = __ldcg(g_xproj + xb + 2 * HID);                               \
        }                                                                      \
        ull acc[4][3];                                                         \
        _Pragma("unroll")                                                      \
        for (int m = 0; m < 4; m++) { acc[m][0]=0; acc[m][1]=0; acc[m][2]=0; } \
        _Pragma("unroll 4")                                                    \
        for (int i = 0; i < 16; i++) {                                         \
            const int kq = i * 8 + q;                                          \
            const float* wp = wcol + kq * 64;                                  \
            ulonglong2 wr = *(const ulonglong2*)(wp);                          \
            ulonglong2 wz = *(const ulonglong2*)(wp + 128 * 64);               \
            ulonglong2 wn = *(const ulonglong2*)(wp + 2 * 128 * 64);           \
            const float* hp = hbase + kq * 4;                                  \
            _Pragma("unroll")                                                  \
            for (int m = 0; m < 4; m++) {                                      \
                ulonglong2 hv = *(const ulonglong2*)(hp + m * GRU_HSTR);       \
                fma2(acc[m][0], hv.x, wr.x); fma2(acc[m][0], hv.y, wr.y);      \
                fma2(acc[m][1], hv.x, wz.x); fma2(acc[m][1], hv.y, wz.y);      \
                fma2(acc[m][2], hv.x, wn.x); fma2(acc[m][2], hv.y, wn.y);      \
            }                                                                  \
        }                                                                      \
        float s[4][3];                                                         \
        _Pragma("unroll")                                                      \
        for (int m = 0; m < 4; m++)                                            \
            _Pragma("unroll")                                                  \
            for (int g = 0; g < 3; g++) {                                      \
                float2 v = unpack2(acc[m][g]);                                 \
                s[m][g] = v.x + v.y;                                           \
            }                                                                  \
        _Pragma("unroll")                                                      \
        for (int off = 1; off <= 4; off <<= 1)                                 \
            _Pragma("unroll")                                                  \
            for (int m = 0; m < 4; m++)                                        \
                _Pragma("unroll")                                              \
                for (int g = 0; g < 3; g++)                                    \
                    s[m][g] += __shfl_xor_sync(0xffffffffu, s[m][g], off);     \
        if (fin) {                                                             \
            float ghr = 0.f, ghz = 0.f, ghn = 0.f;                             \
            _Pragma("unroll")                                                  \
            for (int m = 0; m < 4; m++)                                        \
                if (m == mfin) { ghr=s[m][0]; ghz=s[m][1]; ghn=s[m][2]; }      \
            ghr += bhr; ghz += bhz; ghn += bhn;                                \
            float r = 1.0f / (1.0f + expf(-(xr + ghr)));                       \
            float z = 1.0f / (1.0f + expf(-(xz + ghz)));                       \
            float n = tanhf(xn + r * ghn);                                     \
            float hprev = hbase[mfin * GRU_HSTR + jglob];                      \
            float hnew  = (1.0f - z) * n + z * hprev;                          \
            (NXT)[(size_t)brow * HID + jglob] = hnew;                          \
        }                                                                      \
    } while (0)

    for (int step = 0; step < SEQ; step++) {
        const int cb = step & 1;
        float* nxt = g_h[cb ^ 1];

        // ---- group A: compute + arrive ----
        COMPUTE_GROUP(0, nxt, step);
        __syncthreads();
        if (t == 0) st_rel(&g_bflags[(domA * 32 + jg) * 32], (unsigned)(step + 1));

        // ---- group B: compute + arrive (hides A's barrier RTT) ----
        COMPUTE_GROUP(1, nxt, step);
        __syncthreads();
        if (t == 0) st_rel(&g_bflags[(domB * 32 + jg) * 32], (unsigned)(step + 1));

        // ---- wait A (mostly satisfied) + restage A ----
        if (t >= 32 && t < 64) {
            const unsigned* f = &g_bflags[(domA * 32 + (t - 32)) * 32];
            while (ld_acq(f) < (unsigned)(step + 1)) { }
        }
        __syncthreads();
        for (int r = t; r < 4 * 128; r += 128) {
            int rb = r >> 7, rk = r & 127;
            float4 v = __ldcg((const float4*)(nxt + (size_t)(bgp * 8 + rb) * HID + rk * 4));
            *(float4*)(h_s + rb * GRU_HSTR + rk * 4) = v;
        }

        // ---- wait B (hidden behind waitA+restageA) + restage B ----
        if (t >= 64 && t < 96) {
            const unsigned* f = &g_bflags[(domB * 32 + (t - 64)) * 32];
            while (ld_acq(f) < (unsigned)(step + 1)) { }
        }
        __syncthreads();
        for (int r = t; r < 4 * 128; r += 128) {
            int rb = r >> 7, rk = r & 127;
            float4 v = __ldcg((const float4*)(nxt + (size_t)(bgp * 8 + 4 + rb) * HID + rk * 4));
            *(float4*)(h_s + (4 + rb) * GRU_HSTR + rk * 4) = v;
        }
        __syncthreads();
    }

    // ---- head epilogue: out[b][o] = h[b] . W3[:,o] + b3[o] ----
    // h_s holds final h for rows bgp*8..+8. o in [jg*8,+8).
    {
        const int o  = t & 7;        // 0..7
        const int kc = t >> 3;       // 0..15, k-chunk of 32
        float part[8];
        #pragma unroll
        for (int bb = 0; bb < 8; bb++) part[bb] = 0.f;
        for (int kk = kc * 32; kk < kc * 32 + 32; kk++) {
            float w = __ldg(W3 + (size_t)kk * OUTD + jg * 8 + o);
            #pragma unroll
            for (int bb = 0; bb < 8; bb++)
                part[bb] = fmaf(h_s[bb * GRU_HSTR + kk], w, part[bb]);
        }
        float* red = w_s;  // scratch [16][8][8] (W no longer needed)
        #pragma unroll
        for (int bb = 0; bb < 8; bb++) red[(kc * 8 + o) * 8 + bb] = part[bb];
        __syncthreads();
        if (t < 64) {
            int oo = t & 7, bb = t >> 3;
            float sum = b3[jg * 8 + oo];
            #pragma unroll
            for (int k2 = 0; k2 < 16; k2++) sum += red[(k2 * 8 + oo) * 8 + bb];
            out[(bgp * 8 + bb) * OUTD + jg * 8 + oo] = sum;
        }
    }

    // ---- flag reset (leader jg==0 per bgp zeroes both domains) ----
    __syncthreads();
    if (t == 0) {
        st_rel(&g_bflags[(domA * 32 + jg) * 32], FINALV);
        st_rel(&g_bflags[(domB * 32 + jg) * 32], FINALV);
    }
    if (jg == 0) {
        if (t < 32) {
            const unsigned* f = &g_bflags[(domA * 32 + t) * 32];
            while (ld_acq(f) < FINALV) { }
        } else if (t < 64) {
            const unsigned* f = &g_bflags[(domB * 32 + (t - 32)) * 32];
            while (ld_acq(f) < FINALV) { }
        }
        __syncthreads();
        if (t < 32)
            *(volatile unsigned*)&g_bflags[(domA * 32 + t) * 32] = 0u;
        else if (t < 64)
            *(volatile unsigned*)&g_bflags[(domB * 32 + (t - 32)) * 32] = 0u;
    }
}

// ===========================================================================
extern "C" void kernel_launch(void* const* d_in, const int* in_sizes, int n_in,
                              void* d_out, int out_size)
{
    const int*   input = (const int*)  d_in[0];
    const float* W1    = (const float*)d_in[1];
    const float* b1    = (const float*)d_in[2];
    const float* W2    = (const float*)d_in[3];
    const float* b2    = (const float*)d_in[4];
    const float* W_ih  = (const float*)d_in[5];
    const float* W_hh  = (const float*)d_in[6];
    const float* b_ih  = (const float*)d_in[7];
    const float* b_hh  = (const float*)d_in[8];
    const float* W3    = (const float*)d_in[9];
    const float* b3    = (const float*)d_in[10];
    float* out = (float*)d_out;

    static int configured = 0;
    if (!configured) {
        cudaFuncSetAttribute(gru_kernel,
            cudaFuncAttributeMaxDynamicSharedMemorySize, GRU_SMEMB);
        configured = 1;
    }

    dim3 g1(MROWS / 128, EO / 64);
    gemm_embed_kernel<<<g1, 256>>>(input, W1, b1, W2, b2);

    dim3 g2(MROWS / 128, G3 / 128);
    gemm_xproj_kernel<<<g2, 256>>>(W_ih, b_ih);

    gru_kernel<<<GRU_NCTA, 128, GRU_SMEMB>>>(W_hh, b_hh, W3, b3, out);
}

// round 11
// speedup vs baseline: 1.1062x; 1.1062x over previous
#include <cuda_runtime.h>
#include <cuda_bf16.h>
#include <cstdint>
#include <math.h>

#define SEQ   128
#define BAT   32
#define EH    512
#define EO    256
#define HID   512
#define G3    1536
#define OUTD  256
#define MROWS (SEQ*BAT)
#define THRESH 1e-6f

typedef unsigned long long ull;
typedef unsigned int u32;

// ---------------- scratch (device globals; no allocation allowed) ----------
__device__ float g_emb[MROWS * EO];          // 4 MB
__device__ float g_xproj[MROWS * G3];        // 25 MB
__device__ float g_h[2][BAT * HID];          // ping-pong hidden state
// per-bg barrier state: absolute-valued, reset to 0 at end of each launch
__device__ __align__(128) unsigned g_bflags[128 * 32]; // flag per CTA, 128B apart
__device__ __align__(128) unsigned g_bgen[4 * 32];     // gen per bg group

// ---------------- f32x2 helpers -------------------------------------------
__device__ __forceinline__ ull pack2(float lo, float hi) {
    ull r; asm("mov.b64 %0, {%1, %2};" : "=l"(r) : "f"(lo), "f"(hi)); return r;
}
__device__ __forceinline__ float2 unpack2(ull v) {
    float2 r; asm("mov.b64 {%0, %1}, %2;" : "=f"(r.x), "=f"(r.y) : "l"(v)); return r;
}
__device__ __forceinline__ void fma2(ull& d, ull a, ull b) {
    asm("fma.rn.f32x2 %0, %1, %2, %3;" : "=l"(d) : "l"(a), "l"(b), "l"(d));
}
__device__ __forceinline__ float thr(float v) { return v > THRESH ? v : 0.0f; }

// fast gates: MUFU-based sigmoid / tanh (no libm slow paths)
__device__ __forceinline__ float fast_sigmoid(float x) {
    float e = __expf(-x);
    return __fdividef(1.0f, 1.0f + e);
}
__device__ __forceinline__ float fast_tanh(float x) {
    float e = __expf(-2.0f * x);
    return __fdividef(1.0f - e, 1.0f + e);
}

// ---------------- acquire/release helpers ----------------------------------
__device__ __forceinline__ unsigned ld_acq(const unsigned* p) {
    unsigned v; asm volatile("ld.acquire.gpu.u32 %0, [%1];" : "=r"(v) : "l"(p)); return v;
}
__device__ __forceinline__ void st_rel(unsigned* p, unsigned v) {
    asm volatile("st.release.gpu.u32 [%0], %1;" :: "l"(p), "r"(v));
}

// ===========================================================================
// GEMM 1 (fused embedding): emb = thr( thr(W1[tok]+b1) @ W2 + b2 )
//   M=4096 K=512 N=256. Tile 128x64x16, 256 threads, 8x4 micro-tile (f32x2).
// ===========================================================================
__global__ __launch_bounds__(256) void gemm_embed_kernel(
    const int* __restrict__ tok, const float* __restrict__ W1,
    const float* __restrict__ b1, const float* __restrict__ W2,
    const float* __restrict__ b2)
{
    __shared__ __align__(16) float As[16][132];
    __shared__ __align__(16) float Bs[16][68];

    const int bm = blockIdx.x, bn = blockIdx.y;
    const int t  = threadIdx.x;
    const int tx = t & 15, ty = t >> 4;

    const int arow = t >> 2, aseg = t & 3;
    const int tk0 = tok[bm * 128 + arow];
    const int tk1 = tok[bm * 128 + arow + 64];
    const float* w1r0 = W1 + (size_t)tk0 * EH;
    const float* w1r1 = W1 + (size_t)tk1 * EH;
    const int bk = t >> 4, bseg = t & 15;

    ull acc[8][2] = {};

    for (int kt = 0; kt < EH; kt += 16) {
        float4 bb = *(const float4*)(b1 + kt + aseg * 4);
        float4 a0 = *(const float4*)(w1r0 + kt + aseg * 4);
        float4 a1 = *(const float4*)(w1r1 + kt + aseg * 4);
        a0.x = thr(a0.x + bb.x); a0.y = thr(a0.y + bb.y);
        a0.z = thr(a0.z + bb.z); a0.w = thr(a0.w + bb.w);
        a1.x = thr(a1.x + bb.x); a1.y = thr(a1.y + bb.y);
        a1.z = thr(a1.z + bb.z); a1.w = thr(a1.w + bb.w);
        As[aseg * 4 + 0][arow] = a0.x;  As[aseg * 4 + 0][arow + 64] = a1.x;
        As[aseg * 4 + 1][arow] = a0.y;  As[aseg * 4 + 1][arow + 64] = a1.y;
        As[aseg * 4 + 2][arow] = a0.z;  As[aseg * 4 + 2][arow + 64] = a1.z;
        As[aseg * 4 + 3][arow] = a0.w;  As[aseg * 4 + 3][arow + 64] = a1.w;
        *(float4*)&Bs[bk][bseg * 4] =
            *(const float4*)(W2 + (size_t)(kt + bk) * EO + bn * 64 + bseg * 4);
        __syncthreads();
        #pragma unroll
        for (int kk = 0; kk < 16; kk++) {
            float4 av0 = *(const float4*)&As[kk][ty * 8];
            float4 av1 = *(const float4*)&As[kk][ty * 8 + 4];
            ulonglong2 bv = *(const ulonglong2*)&Bs[kk][tx * 4];
            ull a;
            a = pack2(av0.x, av0.x); fma2(acc[0][0], a, bv.x); fma2(acc[0][1], a, bv.y);
            a = pack2(av0.y, av0.y); fma2(acc[1][0], a, bv.x); fma2(acc[1][1], a, bv.y);
            a = pack2(av0.z, av0.z); fma2(acc[2][0], a, bv.x); fma2(acc[2][1], a, bv.y);
            a = pack2(av0.w, av0.w); fma2(acc[3][0], a, bv.x); fma2(acc[3][1], a, bv.y);
            a = pack2(av1.x, av1.x); fma2(acc[4][0], a, bv.x); fma2(acc[4][1], a, bv.y);
            a = pack2(av1.y, av1.y); fma2(acc[5][0], a, bv.x); fma2(acc[5][1], a, bv.y);
            a = pack2(av1.z, av1.z); fma2(acc[6][0], a, bv.x); fma2(acc[6][1], a, bv.y);
            a = pack2(av1.w, av1.w); fma2(acc[7][0], a, bv.x); fma2(acc[7][1], a, bv.y);
        }
        __syncthreads();
    }
    const int m0 = bm * 128 + ty * 8, n0 = bn * 64 + tx * 4;
    #pragma unroll
    for (int i = 0; i < 8; i++) {
        #pragma unroll
        for (int p = 0; p < 2; p++) {
            float2 v = unpack2(acc[i][p]);
            int n = n0 + p * 2;
            v.x = thr(v.x + b2[n]);
            v.y = thr(v.y + b2[n + 1]);
            *(float2*)&g_emb[(size_t)(m0 + i) * EO + n] = v;
        }
    }
}

// ===========================================================================
// GEMM 2 (NT): xproj = emb @ W_ih^T + b_ih   M=4096 K=256 N=1536
//   Tile 128x128x16, 256 threads, 8x8 micro-tile (f32x2).
//   Launched TWICE with bn_off = 0 and 6 (N halves) so the GRU kernel is
//   the 4th launch in every kernel_launch call (ncu capture alignment).
// ===========================================================================
__global__ __launch_bounds__(256) void gemm_xproj_kernel(
    const float* __restrict__ W_ih, const float* __restrict__ b_ih,
    int bn_off)
{
    __shared__ __align__(16) float As[16][132];
    __shared__ __align__(16) float Bs[16][132];

    const int bm = blockIdx.x, bn = blockIdx.y + bn_off;
    const int t  = threadIdx.x;
    const int tx = t & 15, ty = t >> 4;
    const int row = t >> 2, seg = t & 3;

    ull acc[8][4] = {};

    for (int kt = 0; kt < EO; kt += 16) {
        #pragma unroll
        for (int i = 0; i < 2; i++) {
            int r = row + i * 64;
            float4 a4 = *(const float4*)(g_emb + (size_t)(bm * 128 + r) * EO + kt + seg * 4);
            As[seg * 4 + 0][r] = a4.x;
            As[seg * 4 + 1][r] = a4.y;
            As[seg * 4 + 2][r] = a4.z;
            As[seg * 4 + 3][r] = a4.w;
            float4 b4 = *(const float4*)(W_ih + (size_t)(bn * 128 + r) * EO + kt + seg * 4);
            Bs[seg * 4 + 0][r] = b4.x;
            Bs[seg * 4 + 1][r] = b4.y;
            Bs[seg * 4 + 2][r] = b4.z;
            Bs[seg * 4 + 3][r] = b4.w;
        }
        __syncthreads();
        #pragma unroll
        for (int kk = 0; kk < 16; kk++) {
            float4 av0 = *(const float4*)&As[kk][ty * 8];
            float4 av1 = *(const float4*)&As[kk][ty * 8 + 4];
            ulonglong2 b01 = *(const ulonglong2*)&Bs[kk][tx * 8];
            ulonglong2 b23 = *(const ulonglong2*)&Bs[kk][tx * 8 + 4];
            ull a;
            a = pack2(av0.x, av0.x); fma2(acc[0][0], a, b01.x); fma2(acc[0][1], a, b01.y); fma2(acc[0][2], a, b23.x); fma2(acc[0][3], a, b23.y);
            a = pack2(av0.y, av0.y); fma2(acc[1][0], a, b01.x); fma2(acc[1][1], a, b01.y); fma2(acc[1][2], a, b23.x); fma2(acc[1][3], a, b23.y);
            a = pack2(av0.z, av0.z); fma2(acc[2][0], a, b01.x); fma2(acc[2][1], a, b01.y); fma2(acc[2][2], a, b23.x); fma2(acc[2][3], a, b23.y);
            a = pack2(av0.w, av0.w); fma2(acc[3][0], a, b01.x); fma2(acc[3][1], a, b01.y); fma2(acc[3][2], a, b23.x); fma2(acc[3][3], a, b23.y);
            a = pack2(av1.x, av1.x); fma2(acc[4][0], a, b01.x); fma2(acc[4][1], a, b01.y); fma2(acc[4][2], a, b23.x); fma2(acc[4][3], a, b23.y);
            a = pack2(av1.y, av1.y); fma2(acc[5][0], a, b01.x); fma2(acc[5][1], a, b01.y); fma2(acc[5][2], a, b23.x); fma2(acc[5][3], a, b23.y);
            a = pack2(av1.z, av1.z); fma2(acc[6][0], a, b01.x); fma2(acc[6][1], a, b01.y); fma2(acc[6][2], a, b23.x); fma2(acc[6][3], a, b23.y);
            a = pack2(av1.w, av1.w); fma2(acc[7][0], a, b01.x); fma2(acc[7][1], a, b01.y); fma2(acc[7][2], a, b23.x); fma2(acc[7][3], a, b23.y);
        }
        __syncthreads();
    }
    const int m0 = bm * 128 + ty * 8, n0 = bn * 128 + tx * 8;
    #pragma unroll
    for (int i = 0; i < 8; i++) {
        #pragma unroll
        for (int p = 0; p < 4; p++) {
            float2 v = unpack2(acc[i][p]);
            int n = n0 + p * 2;
            v.x += b_ih[n];
            v.y += b_ih[n + 1];
            *(float2*)&g_xproj[(size_t)(m0 + i) * G3 + n] = v;
        }
    }
}

// ===========================================================================
// GRU recurrence: persistent kernel, 128 CTAs x 128 threads.  (R4 config)
// CTA = (bg 0..3, jg 0..31): owns b in [bg*8,+8), j in [jg*16,+16).
// Thread = (jw 0..15, bh 0..1, ks 0..3): 4 b rows over k-slice kq===ks mod 4;
// W columns XOR-swizzled by kq&3. 2-round shfl reduce over ks.
// Per-bg grid barriers (groups of 32 CTAs), absolute flags + end reset.
// Head GEMM folded into the epilogue.
// ===========================================================================
#define GRU_NCTA   128
#define GRU_WS     (3 * 128 * 16 * 4)      // floats (96 KB)
#define GRU_HSTR   516
#define GRU_SMEMB  ((GRU_WS + 8 * GRU_HSTR) * 4)

__global__ __launch_bounds__(128, 1) void gru_kernel(
    const float* __restrict__ W_hh, const float* __restrict__ b_hh,
    const float* __restrict__ W3,   const float* __restrict__ b3,
    float* __restrict__ out)
{
    extern __shared__ __align__(16) float smem[];
    float* w_s = smem;                 // [gate][kq][col16][4], col swizzled
    float* h_s = smem + GRU_WS;        // [8][516]

    const int t   = threadIdx.x;
    const int bid = blockIdx.x;
    const int jg  = bid & 31;
    const int bg  = bid >> 5;

    // stage W_hh slice, columns swizzled by (kq & 3)
    for (int idx = t; idx < 3 * 16 * 128; idx += 128) {
        int kq = idx & 127;
        int jj = (idx >> 7) & 15;
        int g  = idx >> 11;
        float4 v = *(const float4*)(W_hh + ((size_t)(g * HID + jg * 16 + jj)) * HID + kq * 4);
        int c = (jj + (kq & 3)) & 15;
        *(float4*)(w_s + ((g * 128 + kq) * 16 + c) * 4) = v;
    }
    // zero-init our slice of h buffer 0
    g_h[0][(bg * 8 + (t >> 4)) * HID + jg * 16 + (t & 15)] = 0.0f;

    // ---- per-bg grid barrier: absolute index BI (1..SEQ+1) ----
    #define BG_BAR(BI) do {                                                    \
        __syncthreads();                                                       \
        if (jg == 0) {                                                         \
            if (t >= 1 && t < 32) {                                            \
                const unsigned* f = &g_bflags[(bg * 32 + t) * 32];             \
                while (ld_acq(f) < (unsigned)(BI)) { }                         \
            }                                                                  \
            __syncthreads();                                                   \
            if (t == 0) st_rel(&g_bgen[bg * 32], (unsigned)(BI));              \
        } else {                                                               \
            if (t == 0) {                                                      \
                st_rel(&g_bflags[bid * 32], (unsigned)(BI));                   \
                while (ld_acq(&g_bgen[bg * 32]) < (unsigned)(BI)) { }          \
            }                                                                  \
            __syncthreads();                                                   \
        }                                                                      \
    } while (0)

    BG_BAR(1);

    const int ks = t & 3;
    const int bh = (t >> 2) & 1;
    const int jw = t >> 3;                    // 0..15
    const int jglob = jg * 16 + jw;
    const int bloc  = bh * 4 + ks;            // local b row this thread outputs
    const int bglob = bg * 8 + bloc;          // global batch row

    const float bhr = b_hh[jglob];
    const float bhz = b_hh[HID + jglob];
    const float bhn = b_hh[2 * HID + jglob];

    const float* wcol = w_s + ((jw + ks) & 15) * 4;  // swizzled column base
    const float* hbase = h_s + bh * 4 * GRU_HSTR;

    for (int step = 0; step < SEQ; step++) {
        const float* cur = g_h[step & 1];
        float* nxt = g_h[(step & 1) ^ 1];

        // prefetch this step's xproj early (hide latency behind restage+MMA)
        size_t xb = ((size_t)(step * BAT + bglob)) * G3 + jglob;
        float xr = __ldcg(g_xproj + xb);
        float xz = __ldcg(g_xproj + xb + HID);
        float xn = __ldcg(g_xproj + xb + 2 * HID);

        // restage h slice (written by other SMs -> bypass L1)
        for (int r = t; r < 8 * 128; r += 128) {
            int rb = r >> 7, rk = r & 127;
            float4 v = __ldcg((const float4*)(cur + (size_t)(bg * 8 + rb) * HID + rk * 4));
            *(float4*)(h_s + rb * GRU_HSTR + rk * 4) = v;
        }
        __syncthreads();

        ull acc[4][3];
        #pragma unroll
        for (int m = 0; m < 4; m++) { acc[m][0] = 0; acc[m][1] = 0; acc[m][2] = 0; }

        #pragma unroll 2
        for (int i = 0; i < 32; i++) {
            const int kq = i * 4 + ks;
            const float* wp = wcol + kq * 64;
            ulonglong2 wr = *(const ulonglong2*)(wp);
            ulonglong2 wz = *(const ulonglong2*)(wp + 128 * 64);
            ulonglong2 wn = *(const ulonglong2*)(wp + 2 * 128 * 64);
            const float* hp = hbase + kq * 4;
            #pragma unroll
            for (int m = 0; m < 4; m++) {
                ulonglong2 hv = *(const ulonglong2*)(hp + m * GRU_HSTR);
                fma2(acc[m][0], hv.x, wr.x); fma2(acc[m][0], hv.y, wr.y);
                fma2(acc[m][1], hv.x, wz.x); fma2(acc[m][1], hv.y, wz.y);
                fma2(acc[m][2], hv.x, wn.x); fma2(acc[m][2], hv.y, wn.y);
            }
        }

        // collapse f32x2 halves, reduce over the 4 ks lanes (xor 1, 2)
        float s[4][3];
        #pragma unroll
        for (int m = 0; m < 4; m++)
            #pragma unroll
            for (int g = 0; g < 3; g++) {
                float2 v = unpack2(acc[m][g]);
                s[m][g] = v.x + v.y;
            }
        #pragma unroll
        for (int off = 1; off <= 2; off <<= 1)
            #pragma unroll
            for (int m = 0; m < 4; m++)
                #pragma unroll
                for (int g = 0; g < 3; g++)
                    s[m][g] += __shfl_xor_sync(0xffffffffu, s[m][g], off);

        // thread finalizes b-index m == ks (predicated select)
        float ghr = 0.f, ghz = 0.f, ghn = 0.f;
        #pragma unroll
        for (int m = 0; m < 4; m++)
            if (m == ks) { ghr = s[m][0]; ghz = s[m][1]; ghn = s[m][2]; }
        ghr += bhr; ghz += bhz; ghn += bhn;

        float r = fast_sigmoid(xr + ghr);
        float z = fast_sigmoid(xz + ghz);
        float n = fast_tanh(xn + r * ghn);
        float hprev = h_s[bloc * GRU_HSTR + jglob];
        float hnew  = (1.0f - z) * n + z * hprev;

        nxt[(size_t)bglob * HID + jglob] = hnew;
        BG_BAR(step + 2);
    }

    // ---- head epilogue: out[b][o] = h[b] . W3[:,o] + b3[o] ----
    // CTA covers b in [bg*8,+8), o in [jg*8,+8). SEQ even -> h in g_h[0].
    for (int r = t; r < 8 * 128; r += 128) {
        int rb = r >> 7, rk = r & 127;
        float4 v = __ldcg((const float4*)(g_h[0] + (size_t)(bg * 8 + rb) * HID + rk * 4));
        *(float4*)(h_s + rb * GRU_HSTR + rk * 4) = v;
    }
    __syncthreads();

    {
        const int o  = t & 7;        // 0..7
        const int kc = t >> 3;       // 0..15, k-chunk of 32
        float part[8];
        #pragma unroll
        for (int bb = 0; bb < 8; bb++) part[bb] = 0.f;
        for (int kk = kc * 32; kk < kc * 32 + 32; kk++) {
            float w = __ldg(W3 + (size_t)kk * OUTD + jg * 8 + o);
            #pragma unroll
            for (int bb = 0; bb < 8; bb++)
                part[bb] = fmaf(h_s[bb * GRU_HSTR + kk], w, part[bb]);
        }
        float* red = w_s;  // scratch [16][8][8] (W no longer needed)
        #pragma unroll
        for (int bb = 0; bb < 8; bb++) red[(kc * 8 + o) * 8 + bb] = part[bb];
        __syncthreads();
        if (t < 64) {
            int oo = t & 7, bb = t >> 3;
            float sum = b3[jg * 8 + oo];
            #pragma unroll
            for (int k2 = 0; k2 < 16; k2++) sum += red[(k2 * 8 + oo) * 8 + bb];
            out[(bg * 8 + bb) * OUTD + jg * 8 + oo] = sum;
        }
    }

    // ---- barrier-state reset handshake (so next graph replay sees zeros) ----
    __syncthreads();
    if (jg == 0) {
        if (t >= 1 && t < 32) {
            const unsigned* f = &g_bflags[(bg * 32 + t) * 32];
            while (ld_acq(f) < (unsigned)(SEQ + 2)) { }
        }
        __syncthreads();
        if (t < 32) *(volatile unsigned*)&g_bflags[(bg * 32 + t) * 32] = 0u;
        if (t == 0) *(volatile unsigned*)&g_bgen[bg * 32] = 0u;
    } else {
        if (t == 0) st_rel(&g_bflags[bid * 32], (unsigned)(SEQ + 2));
    }
}

// ===========================================================================
extern "C" void kernel_launch(void* const* d_in, const int* in_sizes, int n_in,
                              void* d_out, int out_size)
{
    const int*   input = (const int*)  d_in[0];
    const float* W1    = (const float*)d_in[1];
    const float* b1    = (const float*)d_in[2];
    const float* W2    = (const float*)d_in[3];
    const float* b2    = (const float*)d_in[4];
    const float* W_ih  = (const float*)d_in[5];
    const float* W_hh  = (const float*)d_in[6];
    const float* b_ih  = (const float*)d_in[7];
    const float* b_hh  = (const float*)d_in[8];
    const float* W3    = (const float*)d_in[9];
    const float* b3    = (const float*)d_in[10];
    float* out = (float*)d_out;

    static int configured = 0;
    if (!configured) {
        cudaFuncSetAttribute(gru_kernel,
            cudaFuncAttributeMaxDynamicSharedMemorySize, GRU_SMEMB);
        configured = 1;
    }

    dim3 g1(MROWS / 128, EO / 64);
    gemm_embed_kernel<<<g1, 256>>>(input, W1, b1, W2, b2);

    // xproj split into two N-halves so gru_kernel is the 4th launch per call
    dim3 g2(MROWS / 128, G3 / 128 / 2);
    gemm_xproj_kernel<<<g2, 256>>>(W_ih, b_ih, 0);
    gemm_xproj_kernel<<<g2, 256>>>(W_ih, b_ih, G3 / 128 / 2);

    gru_kernel<<<GRU_NCTA, 128, GRU_SMEMB>>>(W_hh, b_hh, W3, b3, out);
}

// round 12
// speedup vs baseline: 1.1353x; 1.0263x over previous
#include <cuda_runtime.h>
#include <cuda_bf16.h>
#include <cstdint>
#include <math.h>

#define SEQ   128
#define BAT   32
#define EH    512
#define EO    256
#define HID   512
#define G3    1536
#define OUTD  256
#define MROWS (SEQ*BAT)
#define THRESH 1e-6f

typedef unsigned long long ull;
typedef unsigned int u32;

// ---------------- scratch (device globals; no allocation allowed) ----------
__device__ float g_emb[MROWS * EO];          // 4 MB
__device__ float g_xproj[MROWS * G3];        // 25 MB
__device__ float g_h[2][BAT * HID];          // ping-pong hidden state
// per-bg barrier state: absolute-valued, reset to 0 at end of each launch
__device__ __align__(128) unsigned g_bflags[128 * 32]; // flag per CTA, 128B apart
__device__ __align__(128) unsigned g_bgen[4 * 32];     // gen per bg group

// ---------------- f32x2 helpers -------------------------------------------
__device__ __forceinline__ ull pack2(float lo, float hi) {
    ull r; asm("mov.b64 %0, {%1, %2};" : "=l"(r) : "f"(lo), "f"(hi)); return r;
}
__device__ __forceinline__ float2 unpack2(ull v) {
    float2 r; asm("mov.b64 {%0, %1}, %2;" : "=f"(r.x), "=f"(r.y) : "l"(v)); return r;
}
__device__ __forceinline__ void fma2(ull& d, ull a, ull b) {
    asm("fma.rn.f32x2 %0, %1, %2, %3;" : "=l"(d) : "l"(a), "l"(b), "l"(d));
}
__device__ __forceinline__ float thr(float v) { return v > THRESH ? v : 0.0f; }

// fast gates: MUFU-based sigmoid / tanh (no libm slow paths)
__device__ __forceinline__ float fast_sigmoid(float x) {
    float e = __expf(-x);
    return __fdividef(1.0f, 1.0f + e);
}
__device__ __forceinline__ float fast_tanh(float x) {
    float e = __expf(-2.0f * x);
    return __fdividef(1.0f - e, 1.0f + e);
}

// ---------------- acquire/release helpers ----------------------------------
__device__ __forceinline__ unsigned ld_acq(const unsigned* p) {
    unsigned v; asm volatile("ld.acquire.gpu.u32 %0, [%1];" : "=r"(v) : "l"(p)); return v;
}
__device__ __forceinline__ void st_rel(unsigned* p, unsigned v) {
    asm volatile("st.release.gpu.u32 [%0], %1;" :: "l"(p), "r"(v));
}

// ===========================================================================
// GEMM 1 (fused embedding): emb = thr( thr(W1[tok]+b1) @ W2 + b2 )
//   M=4096 K=512 N=256. Tile 128x64x16, 256 threads, 8x4 micro-tile (f32x2).
// ===========================================================================
__global__ __launch_bounds__(256) void gemm_embed_kernel(
    const int* __restrict__ tok, const float* __restrict__ W1,
    const float* __restrict__ b1, const float* __restrict__ W2,
    const float* __restrict__ b2)
{
    __shared__ __align__(16) float As[16][132];
    __shared__ __align__(16) float Bs[16][68];

    const int bm = blockIdx.x, bn = blockIdx.y;
    const int t  = threadIdx.x;
    const int tx = t & 15, ty = t >> 4;

    const int arow = t >> 2, aseg = t & 3;
    const int tk0 = tok[bm * 128 + arow];
    const int tk1 = tok[bm * 128 + arow + 64];
    const float* w1r0 = W1 + (size_t)tk0 * EH;
    const float* w1r1 = W1 + (size_t)tk1 * EH;
    const int bk = t >> 4, bseg = t & 15;

    ull acc[8][2] = {};

    for (int kt = 0; kt < EH; kt += 16) {
        float4 bb = *(const float4*)(b1 + kt + aseg * 4);
        float4 a0 = *(const float4*)(w1r0 + kt + aseg * 4);
        float4 a1 = *(const float4*)(w1r1 + kt + aseg * 4);
        a0.x = thr(a0.x + bb.x); a0.y = thr(a0.y + bb.y);
        a0.z = thr(a0.z + bb.z); a0.w = thr(a0.w + bb.w);
        a1.x = thr(a1.x + bb.x); a1.y = thr(a1.y + bb.y);
        a1.z = thr(a1.z + bb.z); a1.w = thr(a1.w + bb.w);
        As[aseg * 4 + 0][arow] = a0.x;  As[aseg * 4 + 0][arow + 64] = a1.x;
        As[aseg * 4 + 1][arow] = a0.y;  As[aseg * 4 + 1][arow + 64] = a1.y;
        As[aseg * 4 + 2][arow] = a0.z;  As[aseg * 4 + 2][arow + 64] = a1.z;
        As[aseg * 4 + 3][arow] = a0.w;  As[aseg * 4 + 3][arow + 64] = a1.w;
        *(float4*)&Bs[bk][bseg * 4] =
            *(const float4*)(W2 + (size_t)(kt + bk) * EO + bn * 64 + bseg * 4);
        __syncthreads();
        #pragma unroll
        for (int kk = 0; kk < 16; kk++) {
            float4 av0 = *(const float4*)&As[kk][ty * 8];
            float4 av1 = *(const float4*)&As[kk][ty * 8 + 4];
            ulonglong2 bv = *(const ulonglong2*)&Bs[kk][tx * 4];
            ull a;
            a = pack2(av0.x, av0.x); fma2(acc[0][0], a, bv.x); fma2(acc[0][1], a, bv.y);
            a = pack2(av0.y, av0.y); fma2(acc[1][0], a, bv.x); fma2(acc[1][1], a, bv.y);
            a = pack2(av0.z, av0.z); fma2(acc[2][0], a, bv.x); fma2(acc[2][1], a, bv.y);
            a = pack2(av0.w, av0.w); fma2(acc[3][0], a, bv.x); fma2(acc[3][1], a, bv.y);
            a = pack2(av1.x, av1.x); fma2(acc[4][0], a, bv.x); fma2(acc[4][1], a, bv.y);
            a = pack2(av1.y, av1.y); fma2(acc[5][0], a, bv.x); fma2(acc[5][1], a, bv.y);
            a = pack2(av1.z, av1.z); fma2(acc[6][0], a, bv.x); fma2(acc[6][1], a, bv.y);
            a = pack2(av1.w, av1.w); fma2(acc[7][0], a, bv.x); fma2(acc[7][1], a, bv.y);
        }
        __syncthreads();
    }
    const int m0 = bm * 128 + ty * 8, n0 = bn * 64 + tx * 4;
    #pragma unroll
    for (int i = 0; i < 8; i++) {
        #pragma unroll
        for (int p = 0; p < 2; p++) {
            float2 v = unpack2(acc[i][p]);
            int n = n0 + p * 2;
            v.x = thr(v.x + b2[n]);
            v.y = thr(v.y + b2[n + 1]);
            *(float2*)&g_emb[(size_t)(m0 + i) * EO + n] = v;
        }
    }
}

// ===========================================================================
// GEMM 2 (NT): xproj = emb @ W_ih^T + b_ih   M=4096 K=256 N=1536
//   Tile 128x128x16, 256 threads, 8x8 micro-tile (f32x2).
//   Launched TWICE (N halves) so gru_kernel stays the 4th launch (profiling).
// ===========================================================================
__global__ __launch_bounds__(256) void gemm_xproj_kernel(
    const float* __restrict__ W_ih, const float* __restrict__ b_ih,
    int bn_off)
{
    __shared__ __align__(16) float As[16][132];
    __shared__ __align__(16) float Bs[16][132];

    const int bm = blockIdx.x, bn = blockIdx.y + bn_off;
    const int t  = threadIdx.x;
    const int tx = t & 15, ty = t >> 4;
    const int row = t >> 2, seg = t & 3;

    ull acc[8][4] = {};

    for (int kt = 0; kt < EO; kt += 16) {
        #pragma unroll
        for (int i = 0; i < 2; i++) {
            int r = row + i * 64;
            float4 a4 = *(const float4*)(g_emb + (size_t)(bm * 128 + r) * EO + kt + seg * 4);
            As[seg * 4 + 0][r] = a4.x;
            As[seg * 4 + 1][r] = a4.y;
            As[seg * 4 + 2][r] = a4.z;
            As[seg * 4 + 3][r] = a4.w;
            float4 b4 = *(const float4*)(W_ih + (size_t)(bn * 128 + r) * EO + kt + seg * 4);
            Bs[seg * 4 + 0][r] = b4.x;
            Bs[seg * 4 + 1][r] = b4.y;
            Bs[seg * 4 + 2][r] = b4.z;
            Bs[seg * 4 + 3][r] = b4.w;
        }
        __syncthreads();
        #pragma unroll
        for (int kk = 0; kk < 16; kk++) {
            float4 av0 = *(const float4*)&As[kk][ty * 8];
            float4 av1 = *(const float4*)&As[kk][ty * 8 + 4];
            ulonglong2 b01 = *(const ulonglong2*)&Bs[kk][tx * 8];
            ulonglong2 b23 = *(const ulonglong2*)&Bs[kk][tx * 8 + 4];
            ull a;
            a = pack2(av0.x, av0.x); fma2(acc[0][0], a, b01.x); fma2(acc[0][1], a, b01.y); fma2(acc[0][2], a, b23.x); fma2(acc[0][3], a, b23.y);
            a = pack2(av0.y, av0.y); fma2(acc[1][0], a, b01.x); fma2(acc[1][1], a, b01.y); fma2(acc[1][2], a, b23.x); fma2(acc[1][3], a, b23.y);
            a = pack2(av0.z, av0.z); fma2(acc[2][0], a, b01.x); fma2(acc[2][1], a, b01.y); fma2(acc[2][2], a, b23.x); fma2(acc[2][3], a, b23.y);
            a = pack2(av0.w, av0.w); fma2(acc[3][0], a, b01.x); fma2(acc[3][1], a, b01.y); fma2(acc[3][2], a, b23.x); fma2(acc[3][3], a, b23.y);
            a = pack2(av1.x, av1.x); fma2(acc[4][0], a, b01.x); fma2(acc[4][1], a, b01.y); fma2(acc[4][2], a, b23.x); fma2(acc[4][3], a, b23.y);
            a = pack2(av1.y, av1.y); fma2(acc[5][0], a, b01.x); fma2(acc[5][1], a, b01.y); fma2(acc[5][2], a, b23.x); fma2(acc[5][3], a, b23.y);
            a = pack2(av1.z, av1.z); fma2(acc[6][0], a, b01.x); fma2(acc[6][1], a, b01.y); fma2(acc[6][2], a, b23.x); fma2(acc[6][3], a, b23.y);
            a = pack2(av1.w, av1.w); fma2(acc[7][0], a, b01.x); fma2(acc[7][1], a, b01.y); fma2(acc[7][2], a, b23.x); fma2(acc[7][3], a, b23.y);
        }
        __syncthreads();
    }
    const int m0 = bm * 128 + ty * 8, n0 = bn * 128 + tx * 8;
    #pragma unroll
    for (int i = 0; i < 8; i++) {
        #pragma unroll
        for (int p = 0; p < 4; p++) {
            float2 v = unpack2(acc[i][p]);
            int n = n0 + p * 2;
            v.x += b_ih[n];
            v.y += b_ih[n + 1];
            *(float2*)&g_xproj[(size_t)(m0 + i) * G3 + n] = v;
        }
    }
}

// ===========================================================================
// GRU recurrence: persistent kernel, 128 CTAs x 128 threads. (R4 config +
// register double-buffered inner loop: iteration i+1's 7 LDS.128 are issued
// while iteration i's 24 fma2 execute -> LDS latency hidden, not exposed.)
// ===========================================================================
#define GRU_NCTA   128
#define GRU_WS     (3 * 128 * 16 * 4)      // floats (96 KB)
#define GRU_HSTR   516
#define GRU_SMEMB  ((GRU_WS + 8 * GRU_HSTR) * 4)

__global__ __launch_bounds__(128, 1) void gru_kernel(
    const float* __restrict__ W_hh, const float* __restrict__ b_hh,
    const float* __restrict__ W3,   const float* __restrict__ b3,
    float* __restrict__ out)
{
    extern __shared__ __align__(16) float smem[];
    float* w_s = smem;                 // [gate][kq][col16][4], col swizzled
    float* h_s = smem + GRU_WS;        // [8][516]

    const int t   = threadIdx.x;
    const int bid = blockIdx.x;
    const int jg  = bid & 31;
    const int bg  = bid >> 5;

    // stage W_hh slice, columns swizzled by (kq & 3)
    for (int idx = t; idx < 3 * 16 * 128; idx += 128) {
        int kq = idx & 127;
        int jj = (idx >> 7) & 15;
        int g  = idx >> 11;
        float4 v = *(const float4*)(W_hh + ((size_t)(g * HID + jg * 16 + jj)) * HID + kq * 4);
        int c = (jj + (kq & 3)) & 15;
        *(float4*)(w_s + ((g * 128 + kq) * 16 + c) * 4) = v;
    }
    // zero-init our slice of h buffer 0
    g_h[0][(bg * 8 + (t >> 4)) * HID + jg * 16 + (t & 15)] = 0.0f;

    // ---- per-bg grid barrier: absolute index BI (1..SEQ+1) ----
    #define BG_BAR(BI) do {                                                    \
        __syncthreads();                                                       \
        if (jg == 0) {                                                         \
            if (t >= 1 && t < 32) {                                            \
                const unsigned* f = &g_bflags[(bg * 32 + t) * 32];             \
                while (ld_acq(f) < (unsigned)(BI)) { }                         \
            }                                                                  \
            __syncthreads();                                                   \
            if (t == 0) st_rel(&g_bgen[bg * 32], (unsigned)(BI));              \
        } else {                                                               \
            if (t == 0) {                                                      \
                st_rel(&g_bflags[bid * 32], (unsigned)(BI));                   \
                while (ld_acq(&g_bgen[bg * 32]) < (unsigned)(BI)) { }          \
            }                                                                  \
            __syncthreads();                                                   \
        }                                                                      \
    } while (0)

    BG_BAR(1);

    const int ks = t & 3;
    const int bh = (t >> 2) & 1;
    const int jw = t >> 3;                    // 0..15
    const int jglob = jg * 16 + jw;
    const int bloc  = bh * 4 + ks;            // local b row this thread outputs
    const int bglob = bg * 8 + bloc;          // global batch row

    const float bhr = b_hh[jglob];
    const float bhz = b_hh[HID + jglob];
    const float bhn = b_hh[2 * HID + jglob];

    const float* wcol = w_s + ((jw + ks) & 15) * 4;  // swizzled column base
    const float* hbase = h_s + bh * 4 * GRU_HSTR;

    for (int step = 0; step < SEQ; step++) {
        const float* cur = g_h[step & 1];
        float* nxt = g_h[(step & 1) ^ 1];

        // prefetch this step's xproj early (hide latency behind restage+MMA)
        size_t xb = ((size_t)(step * BAT + bglob)) * G3 + jglob;
        float xr = __ldcg(g_xproj + xb);
        float xz = __ldcg(g_xproj + xb + HID);
        float xn = __ldcg(g_xproj + xb + 2 * HID);

        // restage h slice (written by other SMs -> bypass L1)
        for (int r = t; r < 8 * 128; r += 128) {
            int rb = r >> 7, rk = r & 127;
            float4 v = __ldcg((const float4*)(cur + (size_t)(bg * 8 + rb) * HID + rk * 4));
            *(float4*)(h_s + rb * GRU_HSTR + rk * 4) = v;
        }
        __syncthreads();

        ull acc[4][3];
        #pragma unroll
        for (int m = 0; m < 4; m++) { acc[m][0] = 0; acc[m][1] = 0; acc[m][2] = 0; }

        // ---- register double-buffered MAC loop over 32 k-phases ----
        ulonglong2 cwr, cwz, cwn, chv[4];
        {
            const float* wp = wcol + ks * 64;
            cwr = *(const ulonglong2*)(wp);
            cwz = *(const ulonglong2*)(wp + 128 * 64);
            cwn = *(const ulonglong2*)(wp + 2 * 128 * 64);
            const float* hp = hbase + ks * 4;
            #pragma unroll
            for (int m = 0; m < 4; m++)
                chv[m] = *(const ulonglong2*)(hp + m * GRU_HSTR);
        }
        #pragma unroll 4
        for (int i = 0; i < 31; i++) {
            const int kq = (i + 1) * 4 + ks;
            const float* wp = wcol + kq * 64;
            ulonglong2 nwr = *(const ulonglong2*)(wp);
            ulonglong2 nwz = *(const ulonglong2*)(wp + 128 * 64);
            ulonglong2 nwn = *(const ulonglong2*)(wp + 2 * 128 * 64);
            const float* hp = hbase + kq * 4;
            ulonglong2 nhv[4];
            #pragma unroll
            for (int m = 0; m < 4; m++)
                nhv[m] = *(const ulonglong2*)(hp + m * GRU_HSTR);

            #pragma unroll
            for (int m = 0; m < 4; m++) {
                fma2(acc[m][0], chv[m].x, cwr.x); fma2(acc[m][0], chv[m].y, cwr.y);
                fma2(acc[m][1], chv[m].x, cwz.x); fma2(acc[m][1], chv[m].y, cwz.y);
                fma2(acc[m][2], chv[m].x, cwn.x); fma2(acc[m][2], chv[m].y, cwn.y);
            }
            cwr = nwr; cwz = nwz; cwn = nwn;
            #pragma unroll
            for (int m = 0; m < 4; m++) chv[m] = nhv[m];
        }
        // final iteration (no prefetch)
        #pragma unroll
        for (int m = 0; m < 4; m++) {
            fma2(acc[m][0], chv[m].x, cwr.x); fma2(acc[m][0], chv[m].y, cwr.y);
            fma2(acc[m][1], chv[m].x, cwz.x); fma2(acc[m][1], chv[m].y, cwz.y);
            fma2(acc[m][2], chv[m].x, cwn.x); fma2(acc[m][2], chv[m].y, cwn.y);
        }

        // collapse f32x2 halves, reduce over the 4 ks lanes (xor 1, 2)
        float s[4][3];
        #pragma unroll
        for (int m = 0; m < 4; m++)
            #pragma unroll
            for (int g = 0; g < 3; g++) {
                float2 v = unpack2(acc[m][g]);
                s[m][g] = v.x + v.y;
            }
        #pragma unroll
        for (int off = 1; off <= 2; off <<= 1)
            #pragma unroll
            for (int m = 0; m < 4; m++)
                #pragma unroll
                for (int g = 0; g < 3; g++)
                    s[m][g] += __shfl_xor_sync(0xffffffffu, s[m][g], off);

        // thread finalizes b-index m == ks (predicated select)
        float ghr = 0.f, ghz = 0.f, ghn = 0.f;
        #pragma unroll
        for (int m = 0; m < 4; m++)
            if (m == ks) { ghr = s[m][0]; ghz = s[m][1]; ghn = s[m][2]; }
        ghr += bhr; ghz += bhz; ghn += bhn;

        float r = fast_sigmoid(xr + ghr);
        float z = fast_sigmoid(xz + ghz);
        float n = fast_tanh(xn + r * ghn);
        float hprev = h_s[bloc * GRU_HSTR + jglob];
        float hnew  = (1.0f - z) * n + z * hprev;

        nxt[(size_t)bglob * HID + jglob] = hnew;
        BG_BAR(step + 2);
    }

    // ---- head epilogue: out[b][o] = h[b] . W3[:,o] + b3[o] ----
    // CTA covers b in [bg*8,+8), o in [jg*8,+8). SEQ even -> h in g_h[0].
    for (int r = t; r < 8 * 128; r += 128) {
        int rb = r >> 7, rk = r & 127;
        float4 v = __ldcg((const float4*)(g_h[0] + (size_t)(bg * 8 + rb) * HID + rk * 4));
        *(float4*)(h_s + rb * GRU_HSTR + rk * 4) = v;
    }
    __syncthreads();

    {
        const int o  = t & 7;        // 0..7
        const int kc = t >> 3;       // 0..15, k-chunk of 32
        float part[8];
        #pragma unroll
        for (int bb = 0; bb < 8; bb++) part[bb] = 0.f;
        for (int kk = kc * 32; kk < kc * 32 + 32; kk++) {
            float w = __ldg(W3 + (size_t)kk * OUTD + jg * 8 + o);
            #pragma unroll
            for (int bb = 0; bb < 8; bb++)
                part[bb] = fmaf(h_s[bb * GRU_HSTR + kk], w, part[bb]);
        }
        float* red = w_s;  // scratch [16][8][8] (W no longer needed)
        #pragma unroll
        for (int bb = 0; bb < 8; bb++) red[(kc * 8 + o) * 8 + bb] = part[bb];
        __syncthreads();
        if (t < 64) {
            int oo = t & 7, bb = t >> 3;
            float sum = b3[jg * 8 + oo];
            #pragma unroll
            for (int k2 = 0; k2 < 16; k2++) sum += red[(k2 * 8 + oo) * 8 + bb];
            out[(bg * 8 + bb) * OUTD + jg * 8 + oo] = sum;
        }
    }

    // ---- barrier-state reset handshake (so next graph replay sees zeros) ----
    __syncthreads();
    if (jg == 0) {
        if (t >= 1 && t < 32) {
            const unsigned* f = &g_bflags[(bg * 32 + t) * 32];
            while (ld_acq(f) < (unsigned)(SEQ + 2)) { }
        }
        __syncthreads();
        if (t < 32) *(volatile unsigned*)&g_bflags[(bg * 32 + t) * 32] = 0u;
        if (t == 0) *(volatile unsigned*)&g_bgen[bg * 32] = 0u;
    } else {
        if (t == 0) st_rel(&g_bflags[bid * 32], (unsigned)(SEQ + 2));
    }
}

// ===========================================================================
extern "C" void kernel_launch(void* const* d_in, const int* in_sizes, int n_in,
                              void* d_out, int out_size)
{
    const int*   input = (const int*)  d_in[0];
    const float* W1    = (const float*)d_in[1];
    const float* b1    = (const float*)d_in[2];
    const float* W2    = (const float*)d_in[3];
    const float* b2    = (const float*)d_in[4];
    const float* W_ih  = (const float*)d_in[5];
    const float* W_hh  = (const float*)d_in[6];
    const float* b_ih  = (const float*)d_in[7];
    const float* b_hh  = (const float*)d_in[8];
    const float* W3    = (const float*)d_in[9];
    const float* b3    = (const float*)d_in[10];
    float* out = (float*)d_out;

    static int configured = 0;
    if (!configured) {
        cudaFuncSetAttribute(gru_kernel,
            cudaFuncAttributeMaxDynamicSharedMemorySize, GRU_SMEMB);
        configured = 1;
    }

    dim3 g1(MROWS / 128, EO / 64);
    gemm_embed_kernel<<<g1, 256>>>(input, W1, b1, W2, b2);

    // xproj split into two N-halves so gru_kernel is the 4th launch per call
    dim3 g2(MROWS / 128, G3 / 128 / 2);
    gemm_xproj_kernel<<<g2, 256>>>(W_ih, b_ih, 0);
    gemm_xproj_kernel<<<g2, 256>>>(W_ih, b_ih, G3 / 128 / 2);

    gru_kernel<<<GRU_NCTA, 128, GRU_SMEMB>>>(W_hh, b_hh, W3, b3, out);
}

// round 13
// speedup vs baseline: 1.1531x; 1.0157x over previous
#include <cuda_runtime.h>
#include <cuda_bf16.h>
#include <cstdint>
#include <math.h>

#define SEQ   128
#define BAT   32
#define EH    512
#define EO    256
#define HID   512
#define G3    1536
#define OUTD  256
#define MROWS (SEQ*BAT)
#define THRESH 1e-6f

typedef unsigned long long ull;
typedef unsigned int u32;

// ---------------- scratch (device globals; no allocation allowed) ----------
__device__ float g_emb[MROWS * EO];          // 4 MB
__device__ float g_xproj[MROWS * G3];        // 25 MB
__device__ float g_h[2][BAT * HID];          // ping-pong hidden state
// per-CTA barrier flags (leaderless all-to-all within each bg group of 32)
__device__ __align__(128) unsigned g_bflags[128 * 32]; // flag per CTA, 128B apart

// ---------------- f32x2 helpers -------------------------------------------
__device__ __forceinline__ ull pack2(float lo, float hi) {
    ull r; asm("mov.b64 %0, {%1, %2};" : "=l"(r) : "f"(lo), "f"(hi)); return r;
}
__device__ __forceinline__ float2 unpack2(ull v) {
    float2 r; asm("mov.b64 {%0, %1}, %2;" : "=f"(r.x), "=f"(r.y) : "l"(v)); return r;
}
__device__ __forceinline__ void fma2(ull& d, ull a, ull b) {
    asm("fma.rn.f32x2 %0, %1, %2, %3;" : "=l"(d) : "l"(a), "l"(b), "l"(d));
}
__device__ __forceinline__ float thr(float v) { return v > THRESH ? v : 0.0f; }

// fast gates: MUFU-based sigmoid / tanh (no libm slow paths)
__device__ __forceinline__ float fast_sigmoid(float x) {
    float e = __expf(-x);
    return __fdividef(1.0f, 1.0f + e);
}
__device__ __forceinline__ float fast_tanh(float x) {
    float e = __expf(-2.0f * x);
    return __fdividef(1.0f - e, 1.0f + e);
}

// ---------------- acquire/release helpers ----------------------------------
__device__ __forceinline__ unsigned ld_acq(const unsigned* p) {
    unsigned v; asm volatile("ld.acquire.gpu.u32 %0, [%1];" : "=r"(v) : "l"(p)); return v;
}
__device__ __forceinline__ void st_rel(unsigned* p, unsigned v) {
    asm volatile("st.release.gpu.u32 [%0], %1;" :: "l"(p), "r"(v));
}

// ===========================================================================
// GEMM 1 (fused embedding): emb = thr( thr(W1[tok]+b1) @ W2 + b2 )
//   M=4096 K=512 N=256. Tile 128x64x16, 256 threads, 8x4 micro-tile (f32x2).
// ===========================================================================
__global__ __launch_bounds__(256) void gemm_embed_kernel(
    const int* __restrict__ tok, const float* __restrict__ W1,
    const float* __restrict__ b1, const float* __restrict__ W2,
    const float* __restrict__ b2)
{
    __shared__ __align__(16) float As[16][132];
    __shared__ __align__(16) float Bs[16][68];

    const int bm = blockIdx.x, bn = blockIdx.y;
    const int t  = threadIdx.x;
    const int tx = t & 15, ty = t >> 4;

    const int arow = t >> 2, aseg = t & 3;
    const int tk0 = tok[bm * 128 + arow];
    const int tk1 = tok[bm * 128 + arow + 64];
    const float* w1r0 = W1 + (size_t)tk0 * EH;
    const float* w1r1 = W1 + (size_t)tk1 * EH;
    const int bk = t >> 4, bseg = t & 15;

    ull acc[8][2] = {};

    for (int kt = 0; kt < EH; kt += 16) {
        float4 bb = *(const float4*)(b1 + kt + aseg * 4);
        float4 a0 = *(const float4*)(w1r0 + kt + aseg * 4);
        float4 a1 = *(const float4*)(w1r1 + kt + aseg * 4);
        a0.x = thr(a0.x + bb.x); a0.y = thr(a0.y + bb.y);
        a0.z = thr(a0.z + bb.z); a0.w = thr(a0.w + bb.w);
        a1.x = thr(a1.x + bb.x); a1.y = thr(a1.y + bb.y);
        a1.z = thr(a1.z + bb.z); a1.w = thr(a1.w + bb.w);
        As[aseg * 4 + 0][arow] = a0.x;  As[aseg * 4 + 0][arow + 64] = a1.x;
        As[aseg * 4 + 1][arow] = a0.y;  As[aseg * 4 + 1][arow + 64] = a1.y;
        As[aseg * 4 + 2][arow] = a0.z;  As[aseg * 4 + 2][arow + 64] = a1.z;
        As[aseg * 4 + 3][arow] = a0.w;  As[aseg * 4 + 3][arow + 64] = a1.w;
        *(float4*)&Bs[bk][bseg * 4] =
            *(const float4*)(W2 + (size_t)(kt + bk) * EO + bn * 64 + bseg * 4);
        __syncthreads();
        #pragma unroll
        for (int kk = 0; kk < 16; kk++) {
            float4 av0 = *(const float4*)&As[kk][ty * 8];
            float4 av1 = *(const float4*)&As[kk][ty * 8 + 4];
            ulonglong2 bv = *(const ulonglong2*)&Bs[kk][tx * 4];
            ull a;
            a = pack2(av0.x, av0.x); fma2(acc[0][0], a, bv.x); fma2(acc[0][1], a, bv.y);
            a = pack2(av0.y, av0.y); fma2(acc[1][0], a, bv.x); fma2(acc[1][1], a, bv.y);
            a = pack2(av0.z, av0.z); fma2(acc[2][0], a, bv.x); fma2(acc[2][1], a, bv.y);
            a = pack2(av0.w, av0.w); fma2(acc[3][0], a, bv.x); fma2(acc[3][1], a, bv.y);
            a = pack2(av1.x, av1.x); fma2(acc[4][0], a, bv.x); fma2(acc[4][1], a, bv.y);
            a = pack2(av1.y, av1.y); fma2(acc[5][0], a, bv.x); fma2(acc[5][1], a, bv.y);
            a = pack2(av1.z, av1.z); fma2(acc[6][0], a, bv.x); fma2(acc[6][1], a, bv.y);
            a = pack2(av1.w, av1.w); fma2(acc[7][0], a, bv.x); fma2(acc[7][1], a, bv.y);
        }
        __syncthreads();
    }
    const int m0 = bm * 128 + ty * 8, n0 = bn * 64 + tx * 4;
    #pragma unroll
    for (int i = 0; i < 8; i++) {
        #pragma unroll
        for (int p = 0; p < 2; p++) {
            float2 v = unpack2(acc[i][p]);
            int n = n0 + p * 2;
            v.x = thr(v.x + b2[n]);
            v.y = thr(v.y + b2[n + 1]);
            *(float2*)&g_emb[(size_t)(m0 + i) * EO + n] = v;
        }
    }
}

// ===========================================================================
// GEMM 2 (NT): xproj = emb @ W_ih^T + b_ih   M=4096 K=256 N=1536
//   Tile 128x128x16, 256 threads, 8x8 micro-tile (f32x2).
//   Launched TWICE (N halves) so gru_kernel stays the 4th launch (profiling).
// ===========================================================================
__global__ __launch_bounds__(256) void gemm_xproj_kernel(
    const float* __restrict__ W_ih, const float* __restrict__ b_ih,
    int bn_off)
{
    __shared__ __align__(16) float As[16][132];
    __shared__ __align__(16) float Bs[16][132];

    const int bm = blockIdx.x, bn = blockIdx.y + bn_off;
    const int t  = threadIdx.x;
    const int tx = t & 15, ty = t >> 4;
    const int row = t >> 2, seg = t & 3;

    ull acc[8][4] = {};

    for (int kt = 0; kt < EO; kt += 16) {
        #pragma unroll
        for (int i = 0; i < 2; i++) {
            int r = row + i * 64;
            float4 a4 = *(const float4*)(g_emb + (size_t)(bm * 128 + r) * EO + kt + seg * 4);
            As[seg * 4 + 0][r] = a4.x;
            As[seg * 4 + 1][r] = a4.y;
            As[seg * 4 + 2][r] = a4.z;
            As[seg * 4 + 3][r] = a4.w;
            float4 b4 = *(const float4*)(W_ih + (size_t)(bn * 128 + r) * EO + kt + seg * 4);
            Bs[seg * 4 + 0][r] = b4.x;
            Bs[seg * 4 + 1][r] = b4.y;
            Bs[seg * 4 + 2][r] = b4.z;
            Bs[seg * 4 + 3][r] = b4.w;
        }
        __syncthreads();
        #pragma unroll
        for (int kk = 0; kk < 16; kk++) {
            float4 av0 = *(const float4*)&As[kk][ty * 8];
            float4 av1 = *(const float4*)&As[kk][ty * 8 + 4];
            ulonglong2 b01 = *(const ulonglong2*)&Bs[kk][tx * 8];
            ulonglong2 b23 = *(const ulonglong2*)&Bs[kk][tx * 8 + 4];
            ull a;
            a = pack2(av0.x, av0.x); fma2(acc[0][0], a, b01.x); fma2(acc[0][1], a, b01.y); fma2(acc[0][2], a, b23.x); fma2(acc[0][3], a, b23.y);
            a = pack2(av0.y, av0.y); fma2(acc[1][0], a, b01.x); fma2(acc[1][1], a, b01.y); fma2(acc[1][2], a, b23.x); fma2(acc[1][3], a, b23.y);
            a = pack2(av0.z, av0.z); fma2(acc[2][0], a, b01.x); fma2(acc[2][1], a, b01.y); fma2(acc[2][2], a, b23.x); fma2(acc[2][3], a, b23.y);
            a = pack2(av0.w, av0.w); fma2(acc[3][0], a, b01.x); fma2(acc[3][1], a, b01.y); fma2(acc[3][2], a, b23.x); fma2(acc[3][3], a, b23.y);
            a = pack2(av1.x, av1.x); fma2(acc[4][0], a, b01.x); fma2(acc[4][1], a, b01.y); fma2(acc[4][2], a, b23.x); fma2(acc[4][3], a, b23.y);
            a = pack2(av1.y, av1.y); fma2(acc[5][0], a, b01.x); fma2(acc[5][1], a, b01.y); fma2(acc[5][2], a, b23.x); fma2(acc[5][3], a, b23.y);
            a = pack2(av1.z, av1.z); fma2(acc[6][0], a, b01.x); fma2(acc[6][1], a, b01.y); fma2(acc[6][2], a, b23.x); fma2(acc[6][3], a, b23.y);
            a = pack2(av1.w, av1.w); fma2(acc[7][0], a, b01.x); fma2(acc[7][1], a, b01.y); fma2(acc[7][2], a, b23.x); fma2(acc[7][3], a, b23.y);
        }
        __syncthreads();
    }
    const int m0 = bm * 128 + ty * 8, n0 = bn * 128 + tx * 8;
    #pragma unroll
    for (int i = 0; i < 8; i++) {
        #pragma unroll
        for (int p = 0; p < 4; p++) {
            float2 v = unpack2(acc[i][p]);
            int n = n0 + p * 2;
            v.x += b_ih[n];
            v.y += b_ih[n + 1];
            *(float2*)&g_xproj[(size_t)(m0 + i) * G3 + n] = v;
        }
    }
}

// ===========================================================================
// GRU recurrence: persistent kernel, 128 CTAs x 128 threads.
// Leaderless 1-hop barrier: each CTA release-stores its own flag; lanes 0-31
// poll all 32 group-peer flags directly (no leader/gen hop).
// Depth-2 register-pipelined MAC loop (loads for phase i+2 issued after
// phase i's FMAs -> ~2 iterations of slack over the 29-cyc LDS latency).
// ===========================================================================
#define GRU_NCTA   128
#define GRU_WS     (3 * 128 * 16 * 4)      // floats (96 KB)
#define GRU_HSTR   516
#define GRU_SMEMB  ((GRU_WS + 8 * GRU_HSTR) * 4)

__global__ __launch_bounds__(128, 1) void gru_kernel(
    const float* __restrict__ W_hh, const float* __restrict__ b_hh,
    const float* __restrict__ W3,   const float* __restrict__ b3,
    float* __restrict__ out)
{
    extern __shared__ __align__(16) float smem[];
    float* w_s = smem;                 // [gate][kq][col16][4], col swizzled
    float* h_s = smem + GRU_WS;        // [8][516]

    const int t   = threadIdx.x;
    const int bid = blockIdx.x;
    const int jg  = bid & 31;
    const int bg  = bid >> 5;

    // stage W_hh slice, columns swizzled by (kq & 3)
    for (int idx = t; idx < 3 * 16 * 128; idx += 128) {
        int kq = idx & 127;
        int jj = (idx >> 7) & 15;
        int g  = idx >> 11;
        float4 v = *(const float4*)(W_hh + ((size_t)(g * HID + jg * 16 + jj)) * HID + kq * 4);
        int c = (jj + (kq & 3)) & 15;
        *(float4*)(w_s + ((g * 128 + kq) * 16 + c) * 4) = v;
    }
    // zero-init our slice of h buffer 0
    g_h[0][(bg * 8 + (t >> 4)) * HID + jg * 16 + (t & 15)] = 0.0f;

    // ---- leaderless per-bg grid barrier: 1 store + 1 direct poll ----
    #define BG_BAR(BI) do {                                                    \
        __syncthreads();                                                       \
        if (t == 0) st_rel(&g_bflags[bid * 32], (unsigned)(BI));               \
        if (t < 32) {                                                          \
            const unsigned* f = &g_bflags[(bg * 32 + t) * 32];                 \
            while (ld_acq(f) < (unsigned)(BI)) { }                             \
        }                                                                      \
        __syncthreads();                                                       \
    } while (0)

    BG_BAR(1);

    const int ks = t & 3;
    const int bh = (t >> 2) & 1;
    const int jw = t >> 3;                    // 0..15
    const int jglob = jg * 16 + jw;
    const int bloc  = bh * 4 + ks;            // local b row this thread outputs
    const int bglob = bg * 8 + bloc;          // global batch row

    const float bhr = b_hh[jglob];
    const float bhz = b_hh[HID + jglob];
    const float bhn = b_hh[2 * HID + jglob];

    const float* wcol = w_s + ((jw + ks) & 15) * 4;  // swizzled column base
    const float* hbase = h_s + bh * 4 * GRU_HSTR;

    for (int step = 0; step < SEQ; step++) {
        const float* cur = g_h[step & 1];
        float* nxt = g_h[(step & 1) ^ 1];

        // prefetch this step's xproj early (hide latency behind restage+MMA)
        size_t xb = ((size_t)(step * BAT + bglob)) * G3 + jglob;
        float xr = __ldcg(g_xproj + xb);
        float xz = __ldcg(g_xproj + xb + HID);
        float xn = __ldcg(g_xproj + xb + 2 * HID);

        // restage h slice (written by other SMs -> bypass L1)
        for (int r = t; r < 8 * 128; r += 128) {
            int rb = r >> 7, rk = r & 127;
            float4 v = __ldcg((const float4*)(cur + (size_t)(bg * 8 + rb) * HID + rk * 4));
            *(float4*)(h_s + rb * GRU_HSTR + rk * 4) = v;
        }
        __syncthreads();

        ull acc[4][3];
        #pragma unroll
        for (int m = 0; m < 4; m++) { acc[m][0] = 0; acc[m][1] = 0; acc[m][2] = 0; }

        // ---- depth-2 register-pipelined MAC loop over 32 k-phases ----
        ulonglong2 wb[2][3], hb[2][4];
        #pragma unroll
        for (int p = 0; p < 2; p++) {
            const int kq = p * 4 + ks;
            const float* wp = wcol + kq * 64;
            wb[p][0] = *(const ulonglong2*)(wp);
            wb[p][1] = *(const ulonglong2*)(wp + 128 * 64);
            wb[p][2] = *(const ulonglong2*)(wp + 2 * 128 * 64);
            const float* hp = hbase + kq * 4;
            #pragma unroll
            for (int m = 0; m < 4; m++)
                hb[p][m] = *(const ulonglong2*)(hp + m * GRU_HSTR);
        }
        #pragma unroll 2
        for (int i = 0; i < 32; i++) {
            const int c = i & 1;
            #pragma unroll
            for (int m = 0; m < 4; m++) {
                fma2(acc[m][0], hb[c][m].x, wb[c][0].x); fma2(acc[m][0], hb[c][m].y, wb[c][0].y);
                fma2(acc[m][1], hb[c][m].x, wb[c][1].x); fma2(acc[m][1], hb[c][m].y, wb[c][1].y);
                fma2(acc[m][2], hb[c][m].x, wb[c][2].x); fma2(acc[m][2], hb[c][m].y, wb[c][2].y);
            }
            if (i + 2 < 32) {
                const int kq = (i + 2) * 4 + ks;
                const float* wp = wcol + kq * 64;
                wb[c][0] = *(const ulonglong2*)(wp);
                wb[c][1] = *(const ulonglong2*)(wp + 128 * 64);
                wb[c][2] = *(const ulonglong2*)(wp + 2 * 128 * 64);
                const float* hp = hbase + kq * 4;
                #pragma unroll
                for (int m = 0; m < 4; m++)
                    hb[c][m] = *(const ulonglong2*)(hp + m * GRU_HSTR);
            }
        }

        // collapse f32x2 halves, reduce over the 4 ks lanes (xor 1, 2)
        float s[4][3];
        #pragma unroll
        for (int m = 0; m < 4; m++)
            #pragma unroll
            for (int g = 0; g < 3; g++) {
                float2 v = unpack2(acc[m][g]);
                s[m][g] = v.x + v.y;
            }
        #pragma unroll
        for (int off = 1; off <= 2; off <<= 1)
            #pragma unroll
            for (int m = 0; m < 4; m++)
                #pragma unroll
                for (int g = 0; g < 3; g++)
                    s[m][g] += __shfl_xor_sync(0xffffffffu, s[m][g], off);

        // thread finalizes b-index m == ks (predicated select)
        float ghr = 0.f, ghz = 0.f, ghn = 0.f;
        #pragma unroll
        for (int m = 0; m < 4; m++)
            if (m == ks) { ghr = s[m][0]; ghz = s[m][1]; ghn = s[m][2]; }
        ghr += bhr; ghz += bhz; ghn += bhn;

        float r = fast_sigmoid(xr + ghr);
        float z = fast_sigmoid(xz + ghz);
        float n = fast_tanh(xn + r * ghn);
        float hprev = h_s[bloc * GRU_HSTR + jglob];
        float hnew  = (1.0f - z) * n + z * hprev;

        nxt[(size_t)bglob * HID + jglob] = hnew;
        BG_BAR(step + 2);
    }

    // ---- head epilogue: out[b][o] = h[b] . W3[:,o] + b3[o] ----
    // CTA covers b in [bg*8,+8), o in [jg*8,+8). SEQ even -> h in g_h[0].
    for (int r = t; r < 8 * 128; r += 128) {
        int rb = r >> 7, rk = r & 127;
        float4 v = __ldcg((const float4*)(g_h[0] + (size_t)(bg * 8 + rb) * HID + rk * 4));
        *(float4*)(h_s + rb * GRU_HSTR + rk * 4) = v;
    }
    __syncthreads();

    {
        const int o  = t & 7;        // 0..7
        const int kc = t >> 3;       // 0..15, k-chunk of 32
        float part[8];
        #pragma unroll
        for (int bb = 0; bb < 8; bb++) part[bb] = 0.f;
        for (int kk = kc * 32; kk < kc * 32 + 32; kk++) {
            float w = __ldg(W3 + (size_t)kk * OUTD + jg * 8 + o);
            #pragma unroll
            for (int bb = 0; bb < 8; bb++)
                part[bb] = fmaf(h_s[bb * GRU_HSTR + kk], w, part[bb]);
        }
        float* red = w_s;  // scratch [16][8][8] (W no longer needed)
        #pragma unroll
        for (int bb = 0; bb < 8; bb++) red[(kc * 8 + o) * 8 + bb] = part[bb];
        __syncthreads();
        if (t < 64) {
            int oo = t & 7, bb = t >> 3;
            float sum = b3[jg * 8 + oo];
            #pragma unroll
            for (int k2 = 0; k2 < 16; k2++) sum += red[(k2 * 8 + oo) * 8 + bb];
            out[(bg * 8 + bb) * OUTD + jg * 8 + oo] = sum;
        }
    }

    // ---- flag reset handshake (next graph replay must see zeros) ----
    __syncthreads();
    if (t == 0) st_rel(&g_bflags[bid * 32], (unsigned)(SEQ + 3));
    if (jg == 0) {
        if (t < 32) {
            const unsigned* f = &g_bflags[(bg * 32 + t) * 32];
            while (ld_acq(f) < (unsigned)(SEQ + 3)) { }
        }
        __syncthreads();
        if (t < 32) *(volatile unsigned*)&g_bflags[(bg * 32 + t) * 32] = 0u;
    }
}

// ===========================================================================
extern "C" void kernel_launch(void* const* d_in, const int* in_sizes, int n_in,
                              void* d_out, int out_size)
{
    const int*   input = (const int*)  d_in[0];
    const float* W1    = (const float*)d_in[1];
    const float* b1    = (const float*)d_in[2];
    const float* W2    = (const float*)d_in[3];
    const float* b2    = (const float*)d_in[4];
    const float* W_ih  = (const float*)d_in[5];
    const float* W_hh  = (const float*)d_in[6];
    const float* b_ih  = (const float*)d_in[7];
    const float* b_hh  = (const float*)d_in[8];
    const float* W3    = (const float*)d_in[9];
    const float* b3    = (const float*)d_in[10];
    float* out = (float*)d_out;

    static int configured = 0;
    if (!configured) {
        cudaFuncSetAttribute(gru_kernel,
            cudaFuncAttributeMaxDynamicSharedMemorySize, GRU_SMEMB);
        configured = 1;
    }

    dim3 g1(MROWS / 128, EO / 64);
    gemm_embed_kernel<<<g1, 256>>>(input, W1, b1, W2, b2);

    // xproj split into two N-halves so gru_kernel is the 4th launch per call
    dim3 g2(MROWS / 128, G3 / 128 / 2);
    gemm_xproj_kernel<<<g2, 256>>>(W_ih, b_ih, 0);
    gemm_xproj_kernel<<<g2, 256>>>(W_ih, b_ih, G3 / 128 / 2);

    gru_kernel<<<GRU_NCTA, 128, GRU_SMEMB>>>(W_hh, b_hh, W3, b3, out);
}